// round 3
// baseline (speedup 1.0000x reference)
#include <cuda_runtime.h>
#include <math.h>

// Problem constants
#define Bn   4
#define Sn   2048
#define Dn   1024
#define Mrows (Bn*Sn)          // 8192
#define K2   (2*Dn)            // 2048
#define BSD  (Bn*Sn*Dn)        // 8388608
#define GAMMA 0.01f
#define COND_TH 100.0f

// ---------------- scratch (device globals; allocation-free) ----------------
__device__ float g_psi  [Mrows * K2];        // [8192, 2048]  [Re | Im]
__device__ float g_delta[Mrows * K2];        // [8192, 2048]
__device__ float g_Bmat [2 * K2 * K2];       // per-layer [[Wr-I, Wi],[-Wi, Wr-I]]
__device__ float g_mag  [Mrows * Dn];        // [8192, 1024]
__device__ float g_H    [2 * Bn * Dn * Dn];  // per-layer [B, D, D]
__device__ float g_dampf[2 * Dn];            // (1 - gamma*sum L^2)
// scalars: [0]=sumsq, [4..7]=diffsq[b], [8..11]=prevsq[b],
//          [12..15]=dmax[b], [16..19]=dmin[b], [20..23]=cr[b], [24..27]=ci[b]
__device__ float g_scal[32];

// ---------------- prep kernels ----------------
__global__ void k_buildB(const float* __restrict__ Wr, const float* __restrict__ Wi)
{
    int i = blockIdx.x * 256 + threadIdx.x;        // 2*2048*2048 elements
    int l  = i >> 22;
    int rc = i & 4194303;
    int r = rc >> 11, c = rc & 2047;
    const int WL = l * (Dn * Dn);
    float v;
    if (r < Dn) {
        if (c < Dn) v = Wr[WL + r * Dn + c] - (r == c ? 1.0f : 0.0f);
        else        v = Wi[WL + r * Dn + (c - Dn)];
    } else {
        int rp = r - Dn;
        if (c < Dn) v = -Wi[WL + rp * Dn + c];
        else        v = Wr[WL + rp * Dn + (c - Dn)] - (rp == (c - Dn) ? 1.0f : 0.0f);
    }
    g_Bmat[i] = v;
}

__global__ void k_damp(const float* __restrict__ L)
{
    int t = blockIdx.x * 256 + threadIdx.x;   // 2048
    if (t < 2 * Dn) {
        int l = t >> 10, d = t & 1023;
        float s = 0.f;
        #pragma unroll
        for (int k = 0; k < 4; k++) { float v = L[l * 4096 + k * Dn + d]; s += v * v; }
        g_dampf[t] = 1.0f - GAMMA * s;
    }
}

__global__ void k_init_scal()
{
    int t = threadIdx.x;
    if (t < 32) g_scal[t] = (t >= 16 && t < 20) ? __int_as_float(0x7f800000) : 0.0f;
}

__global__ void k_pack(const float* __restrict__ xr, const float* __restrict__ xi)
{
    int i = blockIdx.x * 256 + threadIdx.x;   // BSD/4
    int m = i >> 8, dq = i & 255;
    *(float4*)&g_psi[m * K2 + dq * 4]      = *(const float4*)&xr[m * Dn + dq * 4];
    *(float4*)&g_psi[m * K2 + Dn + dq * 4] = *(const float4*)&xi[m * Dn + dq * 4];
}

// ---------------- main GEMM: delta = psi @ Bmat[l], fused sum(delta^2) ----------------
#define GBM 128
#define GBN 128
#define GBK 16

__global__ __launch_bounds__(256) void k_gemm_delta(int layer)
{
    const float* __restrict__ A  = g_psi;
    const float* __restrict__ Bm = g_Bmat + (size_t)layer * K2 * K2;
    float* __restrict__ C = g_delta;

    __shared__ float As[GBK][GBM];
    __shared__ float Bs[GBK][GBN];

    const int tid = threadIdx.x;
    const int m0 = blockIdx.y * GBM;
    const int n0 = blockIdx.x * GBN;
    const int tx = tid & 15;
    const int ty = tid >> 4;

    float acc[8][8];
    #pragma unroll
    for (int i = 0; i < 8; i++)
        #pragma unroll
        for (int j = 0; j < 8; j++) acc[i][j] = 0.f;

    float4 pa[2], pb[2];
    // prologue: stage 0
    #pragma unroll
    for (int u = 0; u < 2; u++) {
        int t = tid + u * 256;
        int ar = t >> 2, akq = t & 3;
        pa[u] = *(const float4*)&A[(size_t)(m0 + ar) * K2 + akq * 4];
        int br = t >> 5, bnq = t & 31;
        pb[u] = *(const float4*)&Bm[(size_t)br * K2 + n0 + bnq * 4];
    }

    const int nK = K2 / GBK;  // 128
    for (int kt = 0; kt < nK; kt++) {
        #pragma unroll
        for (int u = 0; u < 2; u++) {
            int t = tid + u * 256;
            int ar = t >> 2, akq = t & 3;
            As[akq * 4 + 0][ar] = pa[u].x;
            As[akq * 4 + 1][ar] = pa[u].y;
            As[akq * 4 + 2][ar] = pa[u].z;
            As[akq * 4 + 3][ar] = pa[u].w;
            int br = t >> 5, bnq = t & 31;
            *(float4*)&Bs[br][bnq * 4] = pb[u];
        }
        __syncthreads();
        if (kt + 1 < nK) {
            int k0 = (kt + 1) * GBK;
            #pragma unroll
            for (int u = 0; u < 2; u++) {
                int t = tid + u * 256;
                int ar = t >> 2, akq = t & 3;
                pa[u] = *(const float4*)&A[(size_t)(m0 + ar) * K2 + k0 + akq * 4];
                int br = t >> 5, bnq = t & 31;
                pb[u] = *(const float4*)&Bm[(size_t)(k0 + br) * K2 + n0 + bnq * 4];
            }
        }
        #pragma unroll
        for (int k = 0; k < GBK; k++) {
            float af[8], bf[8];
            #pragma unroll
            for (int i = 0; i < 8; i++) af[i] = As[k][ty * 8 + i];
            #pragma unroll
            for (int j = 0; j < 8; j++) bf[j] = Bs[k][tx * 8 + j];
            #pragma unroll
            for (int i = 0; i < 8; i++)
                #pragma unroll
                for (int j = 0; j < 8; j++)
                    acc[i][j] += af[i] * bf[j];
        }
        __syncthreads();
    }

    float ss = 0.f;
    #pragma unroll
    for (int i = 0; i < 8; i++) {
        int row = m0 + ty * 8 + i;
        #pragma unroll
        for (int j = 0; j < 8; j += 4) {
            float4 v = make_float4(acc[i][j], acc[i][j+1], acc[i][j+2], acc[i][j+3]);
            *(float4*)&C[(size_t)row * K2 + n0 + tx * 8 + j] = v;
            ss += v.x * v.x + v.y * v.y + v.z * v.z + v.w * v.w;
        }
    }
    #pragma unroll
    for (int o = 16; o > 0; o >>= 1) ss += __shfl_xor_sync(0xffffffffu, ss, o);
    if ((tid & 31) == 0) atomicAdd(&g_scal[0], ss);
}

// ---------------- mag = |delta| * dampf * inv_rms ----------------
__global__ void k_mag(int layer)
{
    int i = blockIdx.x * 256 + threadIdx.x;   // BSD/4
    float ms = g_scal[0] * (1.0f / 8388608.0f);
    ms = fmaxf(ms, 1e-12f);
    float rms = fmaxf(sqrtf(ms), 1e-3f);
    float ir = 1.0f / rms;
    int m = i >> 8, dq = i & 255;
    float4 dr = *(const float4*)&g_delta[m * K2 + dq * 4];
    float4 di = *(const float4*)&g_delta[m * K2 + Dn + dq * 4];
    float4 f  = *(const float4*)&g_dampf[layer * Dn + dq * 4];
    float4 o;
    o.x = sqrtf(dr.x * dr.x + di.x * di.x) * fabsf(f.x) * ir;
    o.y = sqrtf(dr.y * dr.y + di.y * di.y) * fabsf(f.y) * ir;
    o.z = sqrtf(dr.z * dr.z + di.z * di.z) * fabsf(f.z) * ir;
    o.w = sqrtf(dr.w * dr.w + di.w * di.w) * fabsf(f.w) * ir;
    *(float4*)&g_mag[m * Dn + dq * 4] = o;
}

// ---------------- H = mag^T mag / S (per batch) + fused reductions ----------------
__global__ __launch_bounds__(256) void k_H(const float* __restrict__ Hprev_in, int layer)
{
    const int batch = blockIdx.z;
    const float* __restrict__ A = g_mag + (size_t)batch * Sn * Dn;  // [2048, 1024]
    float* __restrict__ H = g_H + (size_t)layer * Bn * Dn * Dn + (size_t)batch * Dn * Dn;
    const float* __restrict__ Hp = (layer == 0)
        ? (Hprev_in + (size_t)batch * Dn * Dn)
        : (g_H + (size_t)batch * Dn * Dn);

    __shared__ float As[GBK][GBM];
    __shared__ float Bs[GBK][GBN];

    const int tid = threadIdx.x;
    const int d0 = blockIdx.y * GBM;
    const int e0 = blockIdx.x * GBN;
    const int tx = tid & 15;
    const int ty = tid >> 4;

    float acc[8][8];
    #pragma unroll
    for (int i = 0; i < 8; i++)
        #pragma unroll
        for (int j = 0; j < 8; j++) acc[i][j] = 0.f;

    float4 pa[2], pb[2];
    #pragma unroll
    for (int u = 0; u < 2; u++) {
        int t = tid + u * 256;
        int sr = t >> 5, q = t & 31;
        pa[u] = *(const float4*)&A[(size_t)sr * Dn + d0 + q * 4];
        pb[u] = *(const float4*)&A[(size_t)sr * Dn + e0 + q * 4];
    }

    const int nK = Sn / GBK;  // 128
    for (int kt = 0; kt < nK; kt++) {
        #pragma unroll
        for (int u = 0; u < 2; u++) {
            int t = tid + u * 256;
            int sr = t >> 5, q = t & 31;
            *(float4*)&As[sr][q * 4] = pa[u];
            *(float4*)&Bs[sr][q * 4] = pb[u];
        }
        __syncthreads();
        if (kt + 1 < nK) {
            int s0 = (kt + 1) * GBK;
            #pragma unroll
            for (int u = 0; u < 2; u++) {
                int t = tid + u * 256;
                int sr = t >> 5, q = t & 31;
                pa[u] = *(const float4*)&A[(size_t)(s0 + sr) * Dn + d0 + q * 4];
                pb[u] = *(const float4*)&A[(size_t)(s0 + sr) * Dn + e0 + q * 4];
            }
        }
        #pragma unroll
        for (int k = 0; k < GBK; k++) {
            float af[8], bf[8];
            #pragma unroll
            for (int i = 0; i < 8; i++) af[i] = As[k][ty * 8 + i];
            #pragma unroll
            for (int j = 0; j < 8; j++) bf[j] = Bs[k][tx * 8 + j];
            #pragma unroll
            for (int i = 0; i < 8; i++)
                #pragma unroll
                for (int j = 0; j < 8; j++)
                    acc[i][j] += af[i] * bf[j];
        }
        __syncthreads();
    }

    const float inv_S = 1.0f / (float)Sn;
    float dsum = 0.f, psum = 0.f;
    #pragma unroll
    for (int i = 0; i < 8; i++) {
        int row = d0 + ty * 8 + i;
        #pragma unroll
        for (int j = 0; j < 8; j += 4) {
            int col = e0 + tx * 8 + j;
            size_t idx = (size_t)row * Dn + col;
            float4 hp = *(const float4*)&Hp[idx];
            float4 h;
            h.x = acc[i][j+0] * inv_S; h.y = acc[i][j+1] * inv_S;
            h.z = acc[i][j+2] * inv_S; h.w = acc[i][j+3] * inv_S;
            *(float4*)&H[idx] = h;
            float d0f = h.x - hp.x, d1 = h.y - hp.y, d2 = h.z - hp.z, d3 = h.w - hp.w;
            dsum += d0f * d0f + d1 * d1 + d2 * d2 + d3 * d3;
            psum += hp.x * hp.x + hp.y * hp.y + hp.z * hp.z + hp.w * hp.w;
            // diagonal elements (H diag >= 0 -> int-compare == float-compare)
            if (row >= col && row < col + 4) {
                float hv = (row == col) ? h.x : (row == col + 1) ? h.y
                         : (row == col + 2) ? h.z : h.w;
                atomicMax((int*)&g_scal[12 + batch], __float_as_int(hv));
                atomicMin((int*)&g_scal[16 + batch], __float_as_int(hv));
            }
        }
    }
    #pragma unroll
    for (int o = 16; o > 0; o >>= 1) {
        dsum += __shfl_xor_sync(0xffffffffu, dsum, o);
        psum += __shfl_xor_sync(0xffffffffu, psum, o);
    }
    if ((tid & 31) == 0) {
        atomicAdd(&g_scal[4 + batch], dsum);
        atomicAdd(&g_scal[8 + batch], psum);
    }
}

// ---------------- per-batch flags -> complex scale; reset scalars ----------------
__global__ void k_flags(const float* __restrict__ theta, const float* __restrict__ js,
                        const float* __restrict__ kth, int layer)
{
    int t = threadIdx.x;
    if (t < Bn) {
        float diffn = sqrtf(g_scal[4 + t]);
        float prevn = sqrtf(g_scal[8 + t]);
        float Kv = diffn / (prevn + 1e-6f);
        float dmax = g_scal[12 + t], dmin = g_scal[16 + t];
        float cond = dmax / (dmin + 1e-12f);
        float cr = (Kv > kth[layer]) ? js[layer] : 1.0f;
        float ci = 0.0f;
        if (cond > COND_TH) {
            float s, c;
            sincosf(theta[layer], &s, &c);
            ci = cr * s; cr = cr * c;
        }
        g_scal[20 + t] = cr; g_scal[24 + t] = ci;
        // reset accumulators for next layer
        g_scal[4 + t] = 0.f; g_scal[8 + t] = 0.f;
        g_scal[12 + t] = 0.f; g_scal[16 + t] = __int_as_float(0x7f800000);
    }
    if (t == 8) g_scal[0] = 0.f;
}

// ---------------- residual update (rms cancels): psi += dampf * delta * c_b ----------------
template <bool LAST>
__global__ void k_update(float* __restrict__ out, int layer)
{
    int i = blockIdx.x * 256 + threadIdx.x;   // BSD/4
    int m = i >> 8, dq = i & 255;
    int batch = m >> 11;
    float cr = g_scal[20 + batch], ci = g_scal[24 + batch];
    float4 dr = *(const float4*)&g_delta[m * K2 + dq * 4];
    float4 di = *(const float4*)&g_delta[m * K2 + Dn + dq * 4];
    float4 f  = *(const float4*)&g_dampf[layer * Dn + dq * 4];
    float4 pr = *(const float4*)&g_psi[m * K2 + dq * 4];
    float4 pi = *(const float4*)&g_psi[m * K2 + Dn + dq * 4];

    pr.x += f.x * (dr.x * cr - di.x * ci);  pi.x += f.x * (dr.x * ci + di.x * cr);
    pr.y += f.y * (dr.y * cr - di.y * ci);  pi.y += f.y * (dr.y * ci + di.y * cr);
    pr.z += f.z * (dr.z * cr - di.z * ci);  pi.z += f.z * (dr.z * ci + di.z * cr);
    pr.w += f.w * (dr.w * cr - di.w * ci);  pi.w += f.w * (dr.w * ci + di.w * cr);

    if (LAST) {
        *(float4*)&out[m * Dn + dq * 4]       = pr;
        *(float4*)&out[BSD + m * Dn + dq * 4] = pi;
    } else {
        *(float4*)&g_psi[m * K2 + dq * 4]      = pr;
        *(float4*)&g_psi[m * K2 + Dn + dq * 4] = pi;
    }
}

// ---------------- launch ----------------
extern "C" void kernel_launch(void* const* d_in, const int* in_sizes, int n_in,
                              void* d_out, int out_size)
{
    const float* x_real = (const float*)d_in[0];
    const float* x_imag = (const float*)d_in[1];
    const float* H_prev = (const float*)d_in[2];
    const float* W_real = (const float*)d_in[3];
    const float* W_imag = (const float*)d_in[4];
    const float* L_ops  = (const float*)d_in[5];
    const float* theta  = (const float*)d_in[6];
    const float* jscale = (const float*)d_in[7];
    const float* kth    = (const float*)d_in[8];
    float* out = (float*)d_out;

    // prep
    k_buildB<<<(2 * K2 * K2) / 256, 256>>>(W_real, W_imag);
    k_damp<<<8, 256>>>(L_ops);
    k_init_scal<<<1, 32>>>();
    k_pack<<<(BSD / 4) / 256, 256>>>(x_real, x_imag);

    dim3 gemm_grid(K2 / GBN, Mrows / GBM);   // (16, 64)
    dim3 H_grid(Dn / GBN, Dn / GBM, Bn);     // (8, 8, 4)
    const int ew_blocks = (BSD / 4) / 256;   // 8192

    // layer 0
    k_gemm_delta<<<gemm_grid, 256>>>(0);
    k_mag<<<ew_blocks, 256>>>(0);
    k_H<<<H_grid, 256>>>(H_prev, 0);
    k_flags<<<1, 32>>>(theta, jscale, kth, 0);
    k_update<false><<<ew_blocks, 256>>>(out, 0);

    // layer 1
    k_gemm_delta<<<gemm_grid, 256>>>(1);
    k_mag<<<ew_blocks, 256>>>(1);
    k_H<<<H_grid, 256>>>(H_prev, 1);
    k_flags<<<1, 32>>>(theta, jscale, kth, 1);
    k_update<true><<<ew_blocks, 256>>>(out, 1);
}

// round 4
// speedup vs baseline: 3.1729x; 3.1729x over previous
#include <cuda_runtime.h>
#include <math.h>

// Problem constants
#define Bn   4
#define Sn   2048
#define Dn   1024
#define Mrows (Bn*Sn)          // 8192
#define K2   (2*Dn)            // 2048
#define BSD  (Bn*Sn*Dn)        // 8388608
#define GAMMA 0.01f
#define COND_TH 100.0f

// ---------------- scratch (device globals; allocation-free) ----------------
__device__ float g_psi  [Mrows * K2];        // [8192, 2048]  [Re | Im]
__device__ float g_delta[Mrows * K2];        // [8192, 2048]
__device__ float g_Bmat [2 * K2 * K2];       // per-layer [[Wr-I, Wi],[-Wi, Wr-I]]
__device__ float g_mag  [Mrows * Dn];        // [8192, 1024]
__device__ float g_H    [2 * Bn * Dn * Dn];  // per-layer [B, D, D]
__device__ float g_dampf[2 * Dn];            // (1 - gamma*sum L^2)
// scalars: [0]=sumsq, [4..7]=diffsq[b], [8..11]=prevsq[b],
//          [12..15]=dmax[b], [16..19]=dmin[b], [20..23]=cr[b], [24..27]=ci[b]
__device__ float g_scal[32];

__device__ __forceinline__ unsigned f2tf(float f)
{
    unsigned r;
    asm("cvt.rna.tf32.f32 %0, %1;" : "=r"(r) : "f"(f));
    return r;
}

__device__ __forceinline__ void mma8(float* c, const unsigned* a, const unsigned* b)
{
    asm("mma.sync.aligned.m16n8k8.row.col.f32.tf32.tf32.f32 "
        "{%0,%1,%2,%3}, {%4,%5,%6,%7}, {%8,%9}, {%0,%1,%2,%3};"
        : "+f"(c[0]), "+f"(c[1]), "+f"(c[2]), "+f"(c[3])
        : "r"(a[0]), "r"(a[1]), "r"(a[2]), "r"(a[3]), "r"(b[0]), "r"(b[1]));
}

// ---------------- prep kernels ----------------
__global__ void k_buildB(const float* __restrict__ Wr, const float* __restrict__ Wi)
{
    int i = blockIdx.x * 256 + threadIdx.x;        // 2*2048*2048 elements
    int l  = i >> 22;
    int rc = i & 4194303;
    int r = rc >> 11, c = rc & 2047;
    const int WL = l * (Dn * Dn);
    float v;
    if (r < Dn) {
        if (c < Dn) v = Wr[WL + r * Dn + c] - (r == c ? 1.0f : 0.0f);
        else        v = Wi[WL + r * Dn + (c - Dn)];
    } else {
        int rp = r - Dn;
        if (c < Dn) v = -Wi[WL + rp * Dn + c];
        else        v = Wr[WL + rp * Dn + (c - Dn)] - (rp == (c - Dn) ? 1.0f : 0.0f);
    }
    g_Bmat[i] = v;
}

__global__ void k_damp(const float* __restrict__ L)
{
    int t = blockIdx.x * 256 + threadIdx.x;   // 2048
    if (t < 2 * Dn) {
        int l = t >> 10, d = t & 1023;
        float s = 0.f;
        #pragma unroll
        for (int k = 0; k < 4; k++) { float v = L[l * 4096 + k * Dn + d]; s += v * v; }
        g_dampf[t] = 1.0f - GAMMA * s;
    }
}

__global__ void k_init_scal()
{
    int t = threadIdx.x;
    if (t < 32) g_scal[t] = (t >= 16 && t < 20) ? __int_as_float(0x7f800000) : 0.0f;
}

__global__ void k_pack(const float* __restrict__ xr, const float* __restrict__ xi)
{
    int i = blockIdx.x * 256 + threadIdx.x;   // BSD/4
    int m = i >> 8, dq = i & 255;
    *(float4*)&g_psi[m * K2 + dq * 4]      = *(const float4*)&xr[m * Dn + dq * 4];
    *(float4*)&g_psi[m * K2 + Dn + dq * 4] = *(const float4*)&xi[m * Dn + dq * 4];
}

// ---------------- main GEMM (TF32 MMA): delta = psi @ Bmat[l], fused sum(delta^2) ----
#define KT 16
#define SP 136    // smem row stride: 136 % 32 == 8 -> conflict-free fragment loads

__global__ __launch_bounds__(256, 2) void k_gemm_delta(int layer)
{
    const float* __restrict__ A  = g_psi;
    const float* __restrict__ Bm = g_Bmat + (size_t)layer * K2 * K2;
    float* __restrict__ C = g_delta;

    __shared__ unsigned As[KT][SP];   // As[k][m]  (transposed A tile)
    __shared__ unsigned Bs[KT][SP];   // Bs[k][n]

    const int tid = threadIdx.x;
    const int m0 = blockIdx.y * 128;
    const int n0 = blockIdx.x * 128;
    const int lane = tid & 31, wid = tid >> 5;
    const int wm = (wid >> 2) * 64;   // warp M offset (2 warps in M)
    const int wn = (wid & 3) * 32;    // warp N offset (4 warps in N)
    const int g = lane >> 2, tig = lane & 3;

    float acc[4][4][4];
    #pragma unroll
    for (int i = 0; i < 4; i++)
        #pragma unroll
        for (int j = 0; j < 4; j++)
            #pragma unroll
            for (int k = 0; k < 4; k++) acc[i][j][k] = 0.f;

    float4 pa[2], pb[2];
    #pragma unroll
    for (int u = 0; u < 2; u++) {
        int idx = tid + u * 256;
        pa[u] = *(const float4*)&A[(size_t)(m0 + (idx >> 2)) * K2 + (idx & 3) * 4];
        pb[u] = *(const float4*)&Bm[(size_t)(idx >> 5) * K2 + n0 + (idx & 31) * 4];
    }

    for (int kt = 0; kt < K2; kt += KT) {
        #pragma unroll
        for (int u = 0; u < 2; u++) {
            int idx = tid + u * 256;
            int ar = idx >> 2, kq = idx & 3;
            As[kq * 4 + 0][ar] = f2tf(pa[u].x);
            As[kq * 4 + 1][ar] = f2tf(pa[u].y);
            As[kq * 4 + 2][ar] = f2tf(pa[u].z);
            As[kq * 4 + 3][ar] = f2tf(pa[u].w);
            int br = idx >> 5, bq = idx & 31;
            uint4 v;
            v.x = f2tf(pb[u].x); v.y = f2tf(pb[u].y);
            v.z = f2tf(pb[u].z); v.w = f2tf(pb[u].w);
            *(uint4*)&Bs[br][bq * 4] = v;
        }
        __syncthreads();
        if (kt + KT < K2) {
            #pragma unroll
            for (int u = 0; u < 2; u++) {
                int idx = tid + u * 256;
                pa[u] = *(const float4*)&A[(size_t)(m0 + (idx >> 2)) * K2 + kt + KT + (idx & 3) * 4];
                pb[u] = *(const float4*)&Bm[(size_t)(kt + KT + (idx >> 5)) * K2 + n0 + (idx & 31) * 4];
            }
        }
        #pragma unroll
        for (int kb = 0; kb < KT; kb += 8) {
            unsigned afr[4][4], bfr[4][2];
            #pragma unroll
            for (int am = 0; am < 4; am++) {
                int m = wm + am * 16 + g;
                afr[am][0] = As[kb + tig][m];
                afr[am][1] = As[kb + tig][m + 8];
                afr[am][2] = As[kb + tig + 4][m];
                afr[am][3] = As[kb + tig + 4][m + 8];
            }
            #pragma unroll
            for (int an = 0; an < 4; an++) {
                int n = wn + an * 8 + g;
                bfr[an][0] = Bs[kb + tig][n];
                bfr[an][1] = Bs[kb + tig + 4][n];
            }
            #pragma unroll
            for (int am = 0; am < 4; am++)
                #pragma unroll
                for (int an = 0; an < 4; an++)
                    mma8(acc[am][an], afr[am], bfr[an]);
        }
        __syncthreads();
    }

    float ss = 0.f;
    #pragma unroll
    for (int am = 0; am < 4; am++) {
        int r0 = m0 + wm + am * 16 + g;
        #pragma unroll
        for (int an = 0; an < 4; an++) {
            int c0 = n0 + wn + an * 8 + 2 * tig;
            float2 v0 = make_float2(acc[am][an][0], acc[am][an][1]);
            float2 v1 = make_float2(acc[am][an][2], acc[am][an][3]);
            *(float2*)&C[(size_t)r0 * K2 + c0]       = v0;
            *(float2*)&C[(size_t)(r0 + 8) * K2 + c0] = v1;
            ss += v0.x * v0.x + v0.y * v0.y + v1.x * v1.x + v1.y * v1.y;
        }
    }
    #pragma unroll
    for (int o = 16; o > 0; o >>= 1) ss += __shfl_xor_sync(0xffffffffu, ss, o);
    if (lane == 0) atomicAdd(&g_scal[0], ss);
}

// ---------------- mag = |delta| * dampf * inv_rms ----------------
__global__ void k_mag(int layer)
{
    int i = blockIdx.x * 256 + threadIdx.x;   // BSD/4
    float ms = g_scal[0] * (1.0f / 8388608.0f);
    ms = fmaxf(ms, 1e-12f);
    float rms = fmaxf(sqrtf(ms), 1e-3f);
    float ir = 1.0f / rms;
    int m = i >> 8, dq = i & 255;
    float4 dr = *(const float4*)&g_delta[m * K2 + dq * 4];
    float4 di = *(const float4*)&g_delta[m * K2 + Dn + dq * 4];
    float4 f  = *(const float4*)&g_dampf[layer * Dn + dq * 4];
    float4 o;
    o.x = sqrtf(dr.x * dr.x + di.x * di.x) * fabsf(f.x) * ir;
    o.y = sqrtf(dr.y * dr.y + di.y * di.y) * fabsf(f.y) * ir;
    o.z = sqrtf(dr.z * dr.z + di.z * di.z) * fabsf(f.z) * ir;
    o.w = sqrtf(dr.w * dr.w + di.w * di.w) * fabsf(f.w) * ir;
    *(float4*)&g_mag[m * Dn + dq * 4] = o;
}

// ---------------- H = mag^T mag / S (TF32 MMA, per batch) + fused reductions ------
__global__ __launch_bounds__(256, 2) void k_H(const float* __restrict__ Hprev_in, int layer)
{
    const int batch = blockIdx.z;
    const float* __restrict__ A = g_mag + (size_t)batch * Sn * Dn;  // [2048, 1024]
    float* __restrict__ H = g_H + (size_t)layer * Bn * Dn * Dn + (size_t)batch * Dn * Dn;
    const float* __restrict__ Hp = (layer == 0)
        ? (Hprev_in + (size_t)batch * Dn * Dn)
        : (g_H + (size_t)batch * Dn * Dn);

    __shared__ unsigned As[KT][SP];   // As[s][d]
    __shared__ unsigned Bs[KT][SP];   // Bs[s][e]

    const int tid = threadIdx.x;
    const int d0 = blockIdx.y * 128;
    const int e0 = blockIdx.x * 128;
    const int lane = tid & 31, wid = tid >> 5;
    const int wm = (wid >> 2) * 64;
    const int wn = (wid & 3) * 32;
    const int g = lane >> 2, tig = lane & 3;

    float acc[4][4][4];
    #pragma unroll
    for (int i = 0; i < 4; i++)
        #pragma unroll
        for (int j = 0; j < 4; j++)
            #pragma unroll
            for (int k = 0; k < 4; k++) acc[i][j][k] = 0.f;

    float4 pa[2], pb[2];
    #pragma unroll
    for (int u = 0; u < 2; u++) {
        int idx = tid + u * 256;
        int sr = idx >> 5, q = idx & 31;
        pa[u] = *(const float4*)&A[(size_t)sr * Dn + d0 + q * 4];
        pb[u] = *(const float4*)&A[(size_t)sr * Dn + e0 + q * 4];
    }

    for (int kt = 0; kt < Sn; kt += KT) {
        #pragma unroll
        for (int u = 0; u < 2; u++) {
            int idx = tid + u * 256;
            int sr = idx >> 5, q = idx & 31;
            uint4 va, vb;
            va.x = f2tf(pa[u].x); va.y = f2tf(pa[u].y); va.z = f2tf(pa[u].z); va.w = f2tf(pa[u].w);
            vb.x = f2tf(pb[u].x); vb.y = f2tf(pb[u].y); vb.z = f2tf(pb[u].z); vb.w = f2tf(pb[u].w);
            *(uint4*)&As[sr][q * 4] = va;
            *(uint4*)&Bs[sr][q * 4] = vb;
        }
        __syncthreads();
        if (kt + KT < Sn) {
            #pragma unroll
            for (int u = 0; u < 2; u++) {
                int idx = tid + u * 256;
                int sr = idx >> 5, q = idx & 31;
                pa[u] = *(const float4*)&A[(size_t)(kt + KT + sr) * Dn + d0 + q * 4];
                pb[u] = *(const float4*)&A[(size_t)(kt + KT + sr) * Dn + e0 + q * 4];
            }
        }
        #pragma unroll
        for (int kb = 0; kb < KT; kb += 8) {
            unsigned afr[4][4], bfr[4][2];
            #pragma unroll
            for (int am = 0; am < 4; am++) {
                int m = wm + am * 16 + g;
                afr[am][0] = As[kb + tig][m];
                afr[am][1] = As[kb + tig][m + 8];
                afr[am][2] = As[kb + tig + 4][m];
                afr[am][3] = As[kb + tig + 4][m + 8];
            }
            #pragma unroll
            for (int an = 0; an < 4; an++) {
                int n = wn + an * 8 + g;
                bfr[an][0] = Bs[kb + tig][n];
                bfr[an][1] = Bs[kb + tig + 4][n];
            }
            #pragma unroll
            for (int am = 0; am < 4; am++)
                #pragma unroll
                for (int an = 0; an < 4; an++)
                    mma8(acc[am][an], afr[am], bfr[an]);
        }
        __syncthreads();
    }

    const float inv_S = 1.0f / (float)Sn;
    float dsum = 0.f, psum = 0.f;
    #pragma unroll
    for (int am = 0; am < 4; am++) {
        #pragma unroll
        for (int half = 0; half < 2; half++) {
            int row = d0 + wm + am * 16 + g + half * 8;
            #pragma unroll
            for (int an = 0; an < 4; an++) {
                int col = e0 + wn + an * 8 + 2 * tig;
                size_t idx = (size_t)row * Dn + col;
                float h0 = acc[am][an][half * 2 + 0] * inv_S;
                float h1 = acc[am][an][half * 2 + 1] * inv_S;
                float2 hp = *(const float2*)&Hp[idx];
                *(float2*)&H[idx] = make_float2(h0, h1);
                float e0f = h0 - hp.x, e1f = h1 - hp.y;
                dsum += e0f * e0f + e1f * e1f;
                psum += hp.x * hp.x + hp.y * hp.y;
                if (row == col) {
                    atomicMax((int*)&g_scal[12 + batch], __float_as_int(h0));
                    atomicMin((int*)&g_scal[16 + batch], __float_as_int(h0));
                } else if (row == col + 1) {
                    atomicMax((int*)&g_scal[12 + batch], __float_as_int(h1));
                    atomicMin((int*)&g_scal[16 + batch], __float_as_int(h1));
                }
            }
        }
    }
    #pragma unroll
    for (int o = 16; o > 0; o >>= 1) {
        dsum += __shfl_xor_sync(0xffffffffu, dsum, o);
        psum += __shfl_xor_sync(0xffffffffu, psum, o);
    }
    if (lane == 0) {
        atomicAdd(&g_scal[4 + batch], dsum);
        atomicAdd(&g_scal[8 + batch], psum);
    }
}

// ---------------- per-batch flags -> complex scale; reset scalars ----------------
__global__ void k_flags(const float* __restrict__ theta, const float* __restrict__ js,
                        const float* __restrict__ kth, int layer)
{
    int t = threadIdx.x;
    if (t < Bn) {
        float diffn = sqrtf(g_scal[4 + t]);
        float prevn = sqrtf(g_scal[8 + t]);
        float Kv = diffn / (prevn + 1e-6f);
        float dmax = g_scal[12 + t], dmin = g_scal[16 + t];
        float cond = dmax / (dmin + 1e-12f);
        float cr = (Kv > kth[layer]) ? js[layer] : 1.0f;
        float ci = 0.0f;
        if (cond > COND_TH) {
            float s, c;
            sincosf(theta[layer], &s, &c);
            ci = cr * s; cr = cr * c;
        }
        g_scal[20 + t] = cr; g_scal[24 + t] = ci;
        g_scal[4 + t] = 0.f; g_scal[8 + t] = 0.f;
        g_scal[12 + t] = 0.f; g_scal[16 + t] = __int_as_float(0x7f800000);
    }
    if (t == 8) g_scal[0] = 0.f;
}

// ---------------- residual update (rms cancels): psi += dampf * delta * c_b -------
template <bool LAST>
__global__ void k_update(float* __restrict__ out, int layer)
{
    int i = blockIdx.x * 256 + threadIdx.x;   // BSD/4
    int m = i >> 8, dq = i & 255;
    int batch = m >> 11;
    float cr = g_scal[20 + batch], ci = g_scal[24 + batch];
    float4 dr = *(const float4*)&g_delta[m * K2 + dq * 4];
    float4 di = *(const float4*)&g_delta[m * K2 + Dn + dq * 4];
    float4 f  = *(const float4*)&g_dampf[layer * Dn + dq * 4];
    float4 pr = *(const float4*)&g_psi[m * K2 + dq * 4];
    float4 pi = *(const float4*)&g_psi[m * K2 + Dn + dq * 4];

    pr.x += f.x * (dr.x * cr - di.x * ci);  pi.x += f.x * (dr.x * ci + di.x * cr);
    pr.y += f.y * (dr.y * cr - di.y * ci);  pi.y += f.y * (dr.y * ci + di.y * cr);
    pr.z += f.z * (dr.z * cr - di.z * ci);  pi.z += f.z * (dr.z * ci + di.z * cr);
    pr.w += f.w * (dr.w * cr - di.w * ci);  pi.w += f.w * (dr.w * ci + di.w * cr);

    if (LAST) {
        *(float4*)&out[m * Dn + dq * 4]       = pr;
        *(float4*)&out[BSD + m * Dn + dq * 4] = pi;
    } else {
        *(float4*)&g_psi[m * K2 + dq * 4]      = pr;
        *(float4*)&g_psi[m * K2 + Dn + dq * 4] = pi;
    }
}

// ---------------- launch ----------------
extern "C" void kernel_launch(void* const* d_in, const int* in_sizes, int n_in,
                              void* d_out, int out_size)
{
    const float* x_real = (const float*)d_in[0];
    const float* x_imag = (const float*)d_in[1];
    const float* H_prev = (const float*)d_in[2];
    const float* W_real = (const float*)d_in[3];
    const float* W_imag = (const float*)d_in[4];
    const float* L_ops  = (const float*)d_in[5];
    const float* theta  = (const float*)d_in[6];
    const float* jscale = (const float*)d_in[7];
    const float* kth    = (const float*)d_in[8];
    float* out = (float*)d_out;

    // prep
    k_buildB<<<(2 * K2 * K2) / 256, 256>>>(W_real, W_imag);
    k_damp<<<8, 256>>>(L_ops);
    k_init_scal<<<1, 32>>>();
    k_pack<<<(BSD / 4) / 256, 256>>>(x_real, x_imag);

    dim3 gemm_grid(K2 / 128, Mrows / 128);   // (16, 64)
    dim3 H_grid(Dn / 128, Dn / 128, Bn);     // (8, 8, 4)
    const int ew_blocks = (BSD / 4) / 256;   // 8192

    // layer 0
    k_gemm_delta<<<gemm_grid, 256>>>(0);
    k_mag<<<ew_blocks, 256>>>(0);
    k_H<<<H_grid, 256>>>(H_prev, 0);
    k_flags<<<1, 32>>>(theta, jscale, kth, 0);
    k_update<false><<<ew_blocks, 256>>>(out, 0);

    // layer 1
    k_gemm_delta<<<gemm_grid, 256>>>(1);
    k_mag<<<ew_blocks, 256>>>(1);
    k_H<<<H_grid, 256>>>(H_prev, 1);
    k_flags<<<1, 32>>>(theta, jscale, kth, 1);
    k_update<true><<<ew_blocks, 256>>>(out, 1);
}

// round 11
// speedup vs baseline: 3.7804x; 1.1915x over previous
#include <cuda_runtime.h>
#include <math.h>

// Problem constants
#define Bn   4
#define Sn   2048
#define Dn   1024
#define Mrows (Bn*Sn)          // 8192
#define K2   (2*Dn)            // 2048
#define BSD  (Bn*Sn*Dn)        // 8388608
#define GAMMA 0.01f
#define COND_TH 100.0f

// ---------------- scratch (device globals; allocation-free) ----------------
__device__ float g_psi [Mrows * K2];          // [8192, 2048]  [Re | Im]
__device__ float g_am  [Mrows * Dn];          // dual-use: A3 = Ar+Ai, then mag
__device__ float g_T   [3 * Mrows * Dn];      // T1, T2, T3  (each [8192,1024])
__device__ float g_B3  [2 * 3 * Dn * Dn];     // per layer: B1=Wr-I, B2=Wi, B3=B1+B2  ([k][n])
__device__ float g_H   [2 * Bn * Dn * Dn];    // per-layer [B, D, D]
__device__ float g_dampf[2 * Dn];             // (1 - gamma*sum L^2)
// [0]=sumsq, [4..7]=diffsq[b], [8..11]=prevsq[b],
// [12..15]=dmax[b], [16..19]=dmin[b], [20..23]=cr[b], [24..27]=ci[b]
__device__ float g_scal[32];

__device__ __forceinline__ unsigned f2tf(float f)
{
    unsigned r;
    asm("cvt.rna.tf32.f32 %0, %1;" : "=r"(r) : "f"(f));
    return r;
}

__device__ __forceinline__ void mma8(float* c, const unsigned* a, const unsigned* b)
{
    asm("mma.sync.aligned.m16n8k8.row.col.f32.tf32.tf32.f32 "
        "{%0,%1,%2,%3}, {%4,%5,%6,%7}, {%8,%9}, {%0,%1,%2,%3};"
        : "+f"(c[0]), "+f"(c[1]), "+f"(c[2]), "+f"(c[3])
        : "r"(a[0]), "r"(a[1]), "r"(a[2]), "r"(a[3]), "r"(b[0]), "r"(b[1]));
}

// ---------------- prep kernels ----------------
// B1 = Wr - I, B2 = Wi, B3 = B1 + B2, all [k][n] per layer
__global__ void k_buildB3(const float* __restrict__ Wr, const float* __restrict__ Wi)
{
    int i = blockIdx.x * 256 + threadIdx.x;       // 2 * 1024 * 1024
    int l = i >> 20;
    int kn = i & 1048575;
    int k = kn >> 10, n = kn & 1023;
    size_t WL = (size_t)l * Dn * Dn + kn;
    float b1 = Wr[WL] - (k == n ? 1.0f : 0.0f);
    float b2 = Wi[WL];
    size_t base = (size_t)l * 3 * Dn * Dn + kn;
    g_B3[base]               = b1;
    g_B3[base + Dn * Dn]     = b2;
    g_B3[base + 2 * Dn * Dn] = b1 + b2;
}

__global__ void k_damp(const float* __restrict__ L)
{
    int t = blockIdx.x * 256 + threadIdx.x;   // 2048
    if (t < 2 * Dn) {
        int l = t >> 10, d = t & 1023;
        float s = 0.f;
        #pragma unroll
        for (int k = 0; k < 4; k++) { float v = L[l * 4096 + k * Dn + d]; s += v * v; }
        g_dampf[t] = 1.0f - GAMMA * s;
    }
}

__global__ void k_init_scal()
{
    int t = threadIdx.x;
    if (t < 32) g_scal[t] = (t >= 16 && t < 20) ? __int_as_float(0x7f800000) : 0.0f;
}

__global__ void k_pack(const float* __restrict__ xr, const float* __restrict__ xi)
{
    int i = blockIdx.x * 256 + threadIdx.x;   // BSD/4
    int m = i >> 8, dq = i & 255;
    float4 r = *(const float4*)&xr[m * Dn + dq * 4];
    float4 im = *(const float4*)&xi[m * Dn + dq * 4];
    *(float4*)&g_psi[m * K2 + dq * 4]      = r;
    *(float4*)&g_psi[m * K2 + Dn + dq * 4] = im;
    float4 a3;
    a3.x = r.x + im.x; a3.y = r.y + im.y; a3.z = r.z + im.z; a3.w = r.w + im.w;
    *(float4*)&g_am[m * Dn + dq * 4] = a3;
}

// ---------------- Karatsuba T GEMMs (TF32 MMA): T_z = A_z @ B_z, K=1024 ----------
#define KT 16
#define SP 136    // smem row stride: 136 % 32 == 8 -> conflict-free fragment loads

__global__ __launch_bounds__(256, 2) void k_gemmT(int layer)
{
    const int z = blockIdx.z;
    const float* __restrict__ A = (z == 0) ? g_psi : (z == 1) ? (g_psi + Dn) : g_am;
    const int lda = (z == 2) ? Dn : K2;
    const float* __restrict__ Bm = g_B3 + ((size_t)layer * 3 + z) * Dn * Dn;
    float* __restrict__ C = g_T + (size_t)z * Mrows * Dn;

    __shared__ unsigned As[KT][SP];   // As[k][m]
    __shared__ unsigned Bs[KT][SP];   // Bs[k][n]

    const int tid = threadIdx.x;
    const int m0 = blockIdx.y * 128;
    const int n0 = blockIdx.x * 128;
    const int lane = tid & 31, wid = tid >> 5;
    const int wm = (wid >> 2) * 64;
    const int wn = (wid & 3) * 32;
    const int g = lane >> 2, tig = lane & 3;

    float acc[4][4][4];
    #pragma unroll
    for (int i = 0; i < 4; i++)
        #pragma unroll
        for (int j = 0; j < 4; j++)
            #pragma unroll
            for (int k = 0; k < 4; k++) acc[i][j][k] = 0.f;

    float4 pa[2], pb[2];
    #pragma unroll
    for (int u = 0; u < 2; u++) {
        int idx = tid + u * 256;
        pa[u] = *(const float4*)&A[(size_t)(m0 + (idx >> 2)) * lda + (idx & 3) * 4];
        pb[u] = *(const float4*)&Bm[(size_t)(idx >> 5) * Dn + n0 + (idx & 31) * 4];
    }

    for (int kt = 0; kt < Dn; kt += KT) {
        #pragma unroll
        for (int u = 0; u < 2; u++) {
            int idx = tid + u * 256;
            int ar = idx >> 2, kq = idx & 3;
            As[kq * 4 + 0][ar] = f2tf(pa[u].x);
            As[kq * 4 + 1][ar] = f2tf(pa[u].y);
            As[kq * 4 + 2][ar] = f2tf(pa[u].z);
            As[kq * 4 + 3][ar] = f2tf(pa[u].w);
            int br = idx >> 5, bq = idx & 31;
            uint4 v;
            v.x = f2tf(pb[u].x); v.y = f2tf(pb[u].y);
            v.z = f2tf(pb[u].z); v.w = f2tf(pb[u].w);
            *(uint4*)&Bs[br][bq * 4] = v;
        }
        __syncthreads();
        if (kt + KT < Dn) {
            #pragma unroll
            for (int u = 0; u < 2; u++) {
                int idx = tid + u * 256;
                pa[u] = *(const float4*)&A[(size_t)(m0 + (idx >> 2)) * lda + kt + KT + (idx & 3) * 4];
                pb[u] = *(const float4*)&Bm[(size_t)(kt + KT + (idx >> 5)) * Dn + n0 + (idx & 31) * 4];
            }
        }
        #pragma unroll
        for (int kb = 0; kb < KT; kb += 8) {
            unsigned afr[4][4], bfr[4][2];
            #pragma unroll
            for (int am = 0; am < 4; am++) {
                int m = wm + am * 16 + g;
                afr[am][0] = As[kb + tig][m];
                afr[am][1] = As[kb + tig][m + 8];
                afr[am][2] = As[kb + tig + 4][m];
                afr[am][3] = As[kb + tig + 4][m + 8];
            }
            #pragma unroll
            for (int an = 0; an < 4; an++) {
                int n = wn + an * 8 + g;
                bfr[an][0] = Bs[kb + tig][n];
                bfr[an][1] = Bs[kb + tig + 4][n];
            }
            #pragma unroll
            for (int am = 0; am < 4; am++)
                #pragma unroll
                for (int an = 0; an < 4; an++)
                    mma8(acc[am][an], afr[am], bfr[an]);
        }
        __syncthreads();
    }

    #pragma unroll
    for (int am = 0; am < 4; am++) {
        int r0 = m0 + wm + am * 16 + g;
        #pragma unroll
        for (int an = 0; an < 4; an++) {
            int c0 = n0 + wn + an * 8 + 2 * tig;
            *(float2*)&C[(size_t)r0 * Dn + c0]       = make_float2(acc[am][an][0], acc[am][an][1]);
            *(float2*)&C[(size_t)(r0 + 8) * Dn + c0] = make_float2(acc[am][an][2], acc[am][an][3]);
        }
    }
}

// ---------------- sumsq of delta (from T1,T2,T3) ----------------
__global__ void k_sumsq()
{
    __shared__ float red[8];
    int i = blockIdx.x * 256 + threadIdx.x;   // BSD/4
    size_t idx = (size_t)i * 4;
    float4 t1 = *(const float4*)&g_T[idx];
    float4 t2 = *(const float4*)&g_T[Mrows * (size_t)Dn + idx];
    float4 t3 = *(const float4*)&g_T[2 * Mrows * (size_t)Dn + idx];
    float s = 0.f;
    { float re = t1.x - t2.x, im = t3.x - t1.x - t2.x; s += re * re + im * im; }
    { float re = t1.y - t2.y, im = t3.y - t1.y - t2.y; s += re * re + im * im; }
    { float re = t1.z - t2.z, im = t3.z - t1.z - t2.z; s += re * re + im * im; }
    { float re = t1.w - t2.w, im = t3.w - t1.w - t2.w; s += re * re + im * im; }
    #pragma unroll
    for (int o = 16; o > 0; o >>= 1) s += __shfl_xor_sync(0xffffffffu, s, o);
    int lane = threadIdx.x & 31, w = threadIdx.x >> 5;
    if (lane == 0) red[w] = s;
    __syncthreads();
    if (w == 0) {
        s = (lane < 8) ? red[lane] : 0.f;
        #pragma unroll
        for (int o = 4; o > 0; o >>= 1) s += __shfl_xor_sync(0xffffffffu, s, o);
        if (lane == 0) atomicAdd(&g_scal[0], s);
    }
}

// ---------------- mag = |delta| * dampf * inv_rms  (overwrites g_am) -------------
__global__ void k_mag(int layer)
{
    int i = blockIdx.x * 256 + threadIdx.x;   // BSD/4
    float ms = g_scal[0] * (1.0f / 8388608.0f);
    ms = fmaxf(ms, 1e-12f);
    float rms = fmaxf(sqrtf(ms), 1e-3f);
    float ir = 1.0f / rms;
    int m = i >> 8, dq = i & 255;
    size_t idx = (size_t)m * Dn + dq * 4;
    float4 t1 = *(const float4*)&g_T[idx];
    float4 t2 = *(const float4*)&g_T[Mrows * (size_t)Dn + idx];
    float4 t3 = *(const float4*)&g_T[2 * Mrows * (size_t)Dn + idx];
    float4 f  = *(const float4*)&g_dampf[layer * Dn + dq * 4];
    float4 o;
    { float re = t1.x - t2.x, im = t3.x - t1.x - t2.x; o.x = sqrtf(re * re + im * im) * fabsf(f.x) * ir; }
    { float re = t1.y - t2.y, im = t3.y - t1.y - t2.y; o.y = sqrtf(re * re + im * im) * fabsf(f.y) * ir; }
    { float re = t1.z - t2.z, im = t3.z - t1.z - t2.z; o.z = sqrtf(re * re + im * im) * fabsf(f.z) * ir; }
    { float re = t1.w - t2.w, im = t3.w - t1.w - t2.w; o.w = sqrtf(re * re + im * im) * fabsf(f.w) * ir; }
    *(float4*)&g_am[idx] = o;
}

// ---------------- H = mag^T mag / S (TF32 MMA, per batch, lower-triangle tiles) ----
__global__ __launch_bounds__(256, 2) void k_H(const float* __restrict__ Hprev_in, int layer)
{
    const int batch = blockIdx.z;
    const float* __restrict__ A = g_am + (size_t)batch * Sn * Dn;  // mag [2048, 1024]
    float* __restrict__ H = g_H + (size_t)layer * Bn * Dn * Dn + (size_t)batch * Dn * Dn;
    const float* __restrict__ Hp = (layer == 0)
        ? (Hprev_in + (size_t)batch * Dn * Dn)
        : (g_H + (size_t)batch * Dn * Dn);

    // triangular tile decode: t -> (ti >= tj)
    const int t = blockIdx.x;
    int ti = 0;
    #pragma unroll
    for (int ii = 1; ii < 8; ii++) if (t >= ii * (ii + 1) / 2) ti = ii;
    const int tj = t - ti * (ti + 1) / 2;
    const int d0 = ti * 128;
    const int e0 = tj * 128;
    const bool offdiag = (ti != tj);

    __shared__ unsigned As[KT][SP];   // As[s][d]
    __shared__ unsigned Bs[KT][SP];   // Bs[s][e]

    const int tid = threadIdx.x;
    const int lane = tid & 31, wid = tid >> 5;
    const int wm = (wid >> 2) * 64;
    const int wn = (wid & 3) * 32;
    const int g = lane >> 2, tig = lane & 3;

    float acc[4][4][4];
    #pragma unroll
    for (int i = 0; i < 4; i++)
        #pragma unroll
        for (int j = 0; j < 4; j++)
            #pragma unroll
            for (int k = 0; k < 4; k++) acc[i][j][k] = 0.f;

    float4 pa[2], pb[2];
    #pragma unroll
    for (int u = 0; u < 2; u++) {
        int idx = tid + u * 256;
        int sr = idx >> 5, q = idx & 31;
        pa[u] = *(const float4*)&A[(size_t)sr * Dn + d0 + q * 4];
        pb[u] = *(const float4*)&A[(size_t)sr * Dn + e0 + q * 4];
    }

    for (int kt = 0; kt < Sn; kt += KT) {
        #pragma unroll
        for (int u = 0; u < 2; u++) {
            int idx = tid + u * 256;
            int sr = idx >> 5, q = idx & 31;
            uint4 va, vb;
            va.x = f2tf(pa[u].x); va.y = f2tf(pa[u].y); va.z = f2tf(pa[u].z); va.w = f2tf(pa[u].w);
            vb.x = f2tf(pb[u].x); vb.y = f2tf(pb[u].y); vb.z = f2tf(pb[u].z); vb.w = f2tf(pb[u].w);
            *(uint4*)&As[sr][q * 4] = va;
            *(uint4*)&Bs[sr][q * 4] = vb;
        }
        __syncthreads();
        if (kt + KT < Sn) {
            #pragma unroll
            for (int u = 0; u < 2; u++) {
                int idx = tid + u * 256;
                int sr = idx >> 5, q = idx & 31;
                pa[u] = *(const float4*)&A[(size_t)(kt + KT + sr) * Dn + d0 + q * 4];
                pb[u] = *(const float4*)&A[(size_t)(kt + KT + sr) * Dn + e0 + q * 4];
            }
        }
        #pragma unroll
        for (int kb = 0; kb < KT; kb += 8) {
            unsigned afr[4][4], bfr[4][2];
            #pragma unroll
            for (int am = 0; am < 4; am++) {
                int m = wm + am * 16 + g;
                afr[am][0] = As[kb + tig][m];
                afr[am][1] = As[kb + tig][m + 8];
                afr[am][2] = As[kb + tig + 4][m];
                afr[am][3] = As[kb + tig + 4][m + 8];
            }
            #pragma unroll
            for (int an = 0; an < 4; an++) {
                int n = wn + an * 8 + g;
                bfr[an][0] = Bs[kb + tig][n];
                bfr[an][1] = Bs[kb + tig + 4][n];
            }
            #pragma unroll
            for (int am = 0; am < 4; am++)
                #pragma unroll
                for (int an = 0; an < 4; an++)
                    mma8(acc[am][an], afr[am], bfr[an]);
        }
        __syncthreads();
    }

    const float inv_S = 1.0f / (float)Sn;
    float dsum = 0.f, psum = 0.f;
    #pragma unroll
    for (int am = 0; am < 4; am++) {
        #pragma unroll
        for (int half = 0; half < 2; half++) {
            int row = d0 + wm + am * 16 + g + half * 8;
            #pragma unroll
            for (int an = 0; an < 4; an++) {
                int col = e0 + wn + an * 8 + 2 * tig;
                size_t idx = (size_t)row * Dn + col;
                float h0 = acc[am][an][half * 2 + 0] * inv_S;
                float h1 = acc[am][an][half * 2 + 1] * inv_S;
                float2 hp = *(const float2*)&Hp[idx];
                *(float2*)&H[idx] = make_float2(h0, h1);
                float e0f = h0 - hp.x, e1f = h1 - hp.y;
                dsum += e0f * e0f + e1f * e1f;
                psum += hp.x * hp.x + hp.y * hp.y;
                if (offdiag) {
                    size_t ti0 = (size_t)col * Dn + row;
                    size_t ti1 = (size_t)(col + 1) * Dn + row;
                    float hpa = Hp[ti0], hpb = Hp[ti1];
                    H[ti0] = h0;
                    H[ti1] = h1;
                    float m0f = h0 - hpa, m1f = h1 - hpb;
                    dsum += m0f * m0f + m1f * m1f;
                    psum += hpa * hpa + hpb * hpb;
                } else {
                    if (row == col) {
                        atomicMax((int*)&g_scal[12 + batch], __float_as_int(h0));
                        atomicMin((int*)&g_scal[16 + batch], __float_as_int(h0));
                    } else if (row == col + 1) {
                        atomicMax((int*)&g_scal[12 + batch], __float_as_int(h1));
                        atomicMin((int*)&g_scal[16 + batch], __float_as_int(h1));
                    }
                }
            }
        }
    }
    #pragma unroll
    for (int o = 16; o > 0; o >>= 1) {
        dsum += __shfl_xor_sync(0xffffffffu, dsum, o);
        psum += __shfl_xor_sync(0xffffffffu, psum, o);
    }
    if (lane == 0) {
        atomicAdd(&g_scal[4 + batch], dsum);
        atomicAdd(&g_scal[8 + batch], psum);
    }
}

// ---------------- per-batch flags -> complex scale; reset scalars ----------------
__global__ void k_flags(const float* __restrict__ theta, const float* __restrict__ js,
                        const float* __restrict__ kth, int layer)
{
    int t = threadIdx.x;
    if (t < Bn) {
        float diffn = sqrtf(g_scal[4 + t]);
        float prevn = sqrtf(g_scal[8 + t]);
        float Kv = diffn / (prevn + 1e-6f);
        float dmax = g_scal[12 + t], dmin = g_scal[16 + t];
        float cond = dmax / (dmin + 1e-12f);
        float cr = (Kv > kth[layer]) ? js[layer] : 1.0f;
        float ci = 0.0f;
        if (cond > COND_TH) {
            float s, c;
            sincosf(theta[layer], &s, &c);
            ci = cr * s; cr = cr * c;
        }
        g_scal[20 + t] = cr; g_scal[24 + t] = ci;
        g_scal[4 + t] = 0.f; g_scal[8 + t] = 0.f;
        g_scal[12 + t] = 0.f; g_scal[16 + t] = __int_as_float(0x7f800000);
    }
    if (t == 8) g_scal[0] = 0.f;
}

// ---------------- residual update: psi += dampf * delta * c_b (rms cancels) -------
template <bool LAST>
__global__ void k_update(float* __restrict__ out, int layer)
{
    int i = blockIdx.x * 256 + threadIdx.x;   // BSD/4
    int m = i >> 8, dq = i & 255;
    int batch = m >> 11;
    float cr = g_scal[20 + batch], ci = g_scal[24 + batch];
    size_t tidx = (size_t)m * Dn + dq * 4;
    float4 t1 = *(const float4*)&g_T[tidx];
    float4 t2 = *(const float4*)&g_T[Mrows * (size_t)Dn + tidx];
    float4 t3 = *(const float4*)&g_T[2 * Mrows * (size_t)Dn + tidx];
    float4 f  = *(const float4*)&g_dampf[layer * Dn + dq * 4];
    float4 pr = *(const float4*)&g_psi[m * K2 + dq * 4];
    float4 pi = *(const float4*)&g_psi[m * K2 + Dn + dq * 4];

    {
        float re = t1.x - t2.x, im = t3.x - t1.x - t2.x;
        pr.x += f.x * (re * cr - im * ci);  pi.x += f.x * (re * ci + im * cr);
    }
    { float re = t1.y - t2.y, im = t3.y - t1.y - t2.y;
      pr.y += f.y * (re * cr - im * ci);  pi.y += f.y * (re * ci + im * cr); }
    { float re = t1.z - t2.z, im = t3.z - t1.z - t2.z;
      pr.z += f.z * (re * cr - im * ci);  pi.z += f.z * (re * ci + im * cr); }
    { float re = t1.w - t2.w, im = t3.w - t1.w - t2.w;
      pr.w += f.w * (re * cr - im * ci);  pi.w += f.w * (re * ci + im * cr); }

    if (LAST) {
        *(float4*)&out[m * Dn + dq * 4]       = pr;
        *(float4*)&out[BSD + m * Dn + dq * 4] = pi;
    } else {
        *(float4*)&g_psi[m * K2 + dq * 4]      = pr;
        *(float4*)&g_psi[m * K2 + Dn + dq * 4] = pi;
        float4 a3;
        a3.x = pr.x + pi.x; a3.y = pr.y + pi.y; a3.z = pr.z + pi.z; a3.w = pr.w + pi.w;
        *(float4*)&g_am[tidx] = a3;
    }
}

// ---------------- launch ----------------
extern "C" void kernel_launch(void* const* d_in, const int* in_sizes, int n_in,
                              void* d_out, int out_size)
{
    const float* x_real = (const float*)d_in[0];
    const float* x_imag = (const float*)d_in[1];
    const float* H_prev = (const float*)d_in[2];
    const float* W_real = (const float*)d_in[3];
    const float* W_imag = (const float*)d_in[4];
    const float* L_ops  = (const float*)d_in[5];
    const float* theta  = (const float*)d_in[6];
    const float* jscale = (const float*)d_in[7];
    const float* kth    = (const float*)d_in[8];
    float* out = (float*)d_out;

    // prep
    k_buildB3<<<(2 * Dn * Dn) / 256, 256>>>(W_real, W_imag);
    k_damp<<<8, 256>>>(L_ops);
    k_init_scal<<<1, 32>>>();
    k_pack<<<(BSD / 4) / 256, 256>>>(x_real, x_imag);

    dim3 gemm_grid(Dn / 128, Mrows / 128, 3);  // (8, 64, 3)
    dim3 H_grid(36, 1, Bn);                    // lower-triangle tiles
    const int ew_blocks = (BSD / 4) / 256;     // 8192

    for (int l = 0; l < 2; l++) {
        k_gemmT<<<gemm_grid, 256>>>(l);
        k_sumsq<<<ew_blocks, 256>>>();
        k_mag<<<ew_blocks, 256>>>(l);
        k_H<<<H_grid, 256>>>(H_prev, l);
        k_flags<<<1, 32>>>(theta, jscale, kth, l);
        if (l == 0) k_update<false><<<ew_blocks, 256>>>(out, l);
        else        k_update<true><<<ew_blocks, 256>>>(out, l);
    }
}